// round 1
// baseline (speedup 1.0000x reference)
#include <cuda_runtime.h>
#include <math.h>

#define HW 16384   // 128*128
#define SDIM 128   // H == W

// ---------------- scratch (static device allocations, ~300 MB) ----------------
__device__ float g_qkv [8L * 192 * HW];   // [b][192][h][w]
__device__ float g_qkvT[8L * 192 * HW];   // [b][192][w][h]
__device__ float g_outT[8L * 64 * HW];    // horizontal branch, [b][c][w][h]
__device__ float g_outV[8L * 64 * HW];    // vertical branch,   [b][c][h][w]
__device__ float g_outS[8L * 64 * HW];    // gamma*(h+v),       [b][c][h][w]

// ---------------- generic batched SGEMM: C[b] = A[M,K] @ B[b][K,N] (+bias)(+resid) ----------------
// N fixed = HW. tile 64x128, BK=16, 256 threads, per-thread 4x8.
__global__ __launch_bounds__(256) void gemm_bias_res(
    const float* __restrict__ A,      // [M,K] row-major (weights)
    const float* __restrict__ Bmat,   // [batch][K,N]
    float*       __restrict__ C,      // [batch][M,N]
    const float* __restrict__ bias,   // [M]
    const float* __restrict__ resid,  // [batch][M,N] or null
    int M, int K)
{
    const int N = HW;
    const int b = blockIdx.z;
    const float* Bb = Bmat + (long)b * K * N;
    float*       Cb = C    + (long)b * M * N;
    const float* Rb = resid ? resid + (long)b * M * N : nullptr;

    const int n0 = blockIdx.x * 128;
    const int m0 = blockIdx.y * 64;

    __shared__ float As[16][65];    // [k][m]
    __shared__ float Bs[16][128];   // [k][n]

    const int tid = threadIdx.x;
    const int tx = tid & 15;        // n-group
    const int ty = tid >> 4;        // m-group

    float acc[4][8];
#pragma unroll
    for (int i = 0; i < 4; i++)
#pragma unroll
        for (int j = 0; j < 8; j++) acc[i][j] = 0.f;

    const int ac = tid & 15;        // k within chunk
    const int ar = tid >> 4;        // row base

    for (int k0 = 0; k0 < K; k0 += 16) {
#pragma unroll
        for (int i = 0; i < 4; i++)
            As[ac][ar + 16 * i] = A[(m0 + ar + 16 * i) * K + k0 + ac];
#pragma unroll
        for (int i = 0; i < 2; i++) {
            int fi = tid + i * 256;
            int br = fi >> 5;
            int bc = (fi & 31) * 4;
            *(float4*)&Bs[br][bc] = *(const float4*)&Bb[(long)(k0 + br) * N + n0 + bc];
        }
        __syncthreads();

#pragma unroll
        for (int k = 0; k < 16; k++) {
            float a0 = As[k][ty * 4 + 0];
            float a1 = As[k][ty * 4 + 1];
            float a2 = As[k][ty * 4 + 2];
            float a3 = As[k][ty * 4 + 3];
            float4 b0 = *(float4*)&Bs[k][tx * 8];
            float4 b1 = *(float4*)&Bs[k][tx * 8 + 4];
            float bb[8] = {b0.x, b0.y, b0.z, b0.w, b1.x, b1.y, b1.z, b1.w};
#pragma unroll
            for (int j = 0; j < 8; j++) {
                acc[0][j] = fmaf(a0, bb[j], acc[0][j]);
                acc[1][j] = fmaf(a1, bb[j], acc[1][j]);
                acc[2][j] = fmaf(a2, bb[j], acc[2][j]);
                acc[3][j] = fmaf(a3, bb[j], acc[3][j]);
            }
        }
        __syncthreads();
    }

#pragma unroll
    for (int i = 0; i < 4; i++) {
        int m = m0 + ty * 4 + i;
        float bm = bias[m];
        long rowoff = (long)m * N + n0 + tx * 8;
        float4 o0, o1;
        float v[8];
#pragma unroll
        for (int j = 0; j < 8; j++) v[j] = acc[i][j] + bm;
        if (Rb) {
            float4 r0 = *(const float4*)&Rb[rowoff];
            float4 r1 = *(const float4*)&Rb[rowoff + 4];
            v[0] += r0.x; v[1] += r0.y; v[2] += r0.z; v[3] += r0.w;
            v[4] += r1.x; v[5] += r1.y; v[6] += r1.z; v[7] += r1.w;
        }
        o0.x = v[0]; o0.y = v[1]; o0.z = v[2]; o0.w = v[3];
        o1.x = v[4]; o1.y = v[5]; o1.z = v[6]; o1.w = v[7];
        *(float4*)&Cb[rowoff]     = o0;
        *(float4*)&Cb[rowoff + 4] = o1;
    }
}

// ---------------- 128x128 HW-transpose per slice ----------------
__global__ __launch_bounds__(256) void transpose_hw(const float* __restrict__ in,
                                                    float* __restrict__ out)
{
    __shared__ float tile[32][33];
    const long base = (long)blockIdx.z * HW;
    const int bx = blockIdx.x * 32;
    const int by = blockIdx.y * 32;
    const int tx = threadIdx.x;
    const int ty = threadIdx.y;   // 32 x 8
#pragma unroll
    for (int i = 0; i < 32; i += 8)
        tile[ty + i][tx] = in[base + (long)(by + ty + i) * SDIM + bx + tx];
    __syncthreads();
#pragma unroll
    for (int i = 0; i < 32; i += 8)
        out[base + (long)(bx + ty + i) * SDIM + by + tx] = tile[tx][ty + i];
}

// ---------------- attention branch: one block per (b, s) ----------------
// qkv slice layout: qkv[base + ch*HW + s*128 + t]   (t contiguous)
// Q = ch 0..63, K = ch 64..127, V = ch 128..191
// out[obase + c*HW + s*128 + t] = sum_j softmax(QK^T)[c][j] * V[j][t]
__global__ __launch_bounds__(256) void attn_kernel(const float* __restrict__ qkv,
                                                   float* __restrict__ outp)
{
    extern __shared__ float sm[];
    float* Qs = sm;                 // [64][132]  (later reused for V)
    float* Ks = sm + 64 * 132;      // [64][132]
    float* Es = sm + 2 * 64 * 132;  // [64][65]

    const int b = blockIdx.y;
    const int s = blockIdx.x;
    const int tid = threadIdx.x;
    const long base = (long)b * 192 * HW + (long)s * SDIM;

    // load Q and K (each 2048 float4, 8 per thread)
#pragma unroll
    for (int t = 0; t < 8; t++) {
        int fi = tid + t * 256;
        int row = fi >> 5;
        int c4 = (fi & 31) * 4;
        *(float4*)&Qs[row * 132 + c4] = *(const float4*)&qkv[base + (long)row * HW + c4];
        *(float4*)&Ks[row * 132 + c4] = *(const float4*)&qkv[base + (long)(row + 64) * HW + c4];
    }
    __syncthreads();

    // energy: E[i][j] = sum_h Q[i][h]*K[j][h]
    {
        const int ti = tid & 15;
        const int tj = tid >> 4;
        float acc[4][4];
#pragma unroll
        for (int i = 0; i < 4; i++)
#pragma unroll
            for (int j = 0; j < 4; j++) acc[i][j] = 0.f;

        for (int h = 0; h < 128; h += 4) {
            float4 qv[4], kv[4];
#pragma unroll
            for (int i = 0; i < 4; i++) qv[i] = *(float4*)&Qs[(ti + 16 * i) * 132 + h];
#pragma unroll
            for (int j = 0; j < 4; j++) kv[j] = *(float4*)&Ks[(tj + 16 * j) * 132 + h];
#pragma unroll
            for (int i = 0; i < 4; i++)
#pragma unroll
                for (int j = 0; j < 4; j++) {
                    acc[i][j] = fmaf(qv[i].x, kv[j].x, acc[i][j]);
                    acc[i][j] = fmaf(qv[i].y, kv[j].y, acc[i][j]);
                    acc[i][j] = fmaf(qv[i].z, kv[j].z, acc[i][j]);
                    acc[i][j] = fmaf(qv[i].w, kv[j].w, acc[i][j]);
                }
        }
#pragma unroll
        for (int i = 0; i < 4; i++)
#pragma unroll
            for (int j = 0; j < 4; j++)
                Es[(ti + 16 * i) * 65 + tj + 16 * j] = acc[i][j];
    }
    __syncthreads();

    // load V into Qs buffer (all threads), softmax on rows (tid < 64)
#pragma unroll
    for (int t = 0; t < 8; t++) {
        int fi = tid + t * 256;
        int row = fi >> 5;
        int c4 = (fi & 31) * 4;
        *(float4*)&Qs[row * 132 + c4] = *(const float4*)&qkv[base + (long)(row + 128) * HW + c4];
    }
    if (tid < 64) {
        float* row = &Es[tid * 65];
        float m = -INFINITY;
#pragma unroll
        for (int j = 0; j < 64; j++) m = fmaxf(m, row[j]);
        float ssum = 0.f;
#pragma unroll
        for (int j = 0; j < 64; j++) { float e = __expf(row[j] - m); row[j] = e; ssum += e; }
        float inv = 1.f / ssum;
#pragma unroll
        for (int j = 0; j < 64; j++) row[j] *= inv;
    }
    __syncthreads();

    // AV: warp w handles rows [w*8, w*8+8), lane covers t = lane + 32*hh
    {
        const int warp = tid >> 5;
        const int lane = tid & 31;
        const int i0 = warp * 8;
        float o[8][4];
#pragma unroll
        for (int r = 0; r < 8; r++)
#pragma unroll
            for (int hh = 0; hh < 4; hh++) o[r][hh] = 0.f;

        for (int j = 0; j < 64; j++) {
            float a[8];
#pragma unroll
            for (int r = 0; r < 8; r++) a[r] = Es[(i0 + r) * 65 + j];
            float v[4];
#pragma unroll
            for (int hh = 0; hh < 4; hh++) v[hh] = Qs[j * 132 + hh * 32 + lane];
#pragma unroll
            for (int r = 0; r < 8; r++)
#pragma unroll
                for (int hh = 0; hh < 4; hh++)
                    o[r][hh] = fmaf(a[r], v[hh], o[r][hh]);
        }

        const long obase = (long)b * 64 * HW + (long)s * SDIM;
#pragma unroll
        for (int r = 0; r < 8; r++)
#pragma unroll
            for (int hh = 0; hh < 4; hh++)
                outp[obase + (long)(i0 + r) * HW + hh * 32 + lane] = o[r][hh];
    }
}

// ---------------- combine: outS[b][c][h][w] = gamma*(outV[b][c][h][w] + outT[b][c][w][h]) ----------------
__global__ __launch_bounds__(256) void combine_kernel(const float* __restrict__ outV,
                                                      const float* __restrict__ outT,
                                                      const float* __restrict__ gamma,
                                                      float* __restrict__ outS)
{
    __shared__ float tile[32][33];
    const long base = (long)blockIdx.z * HW;
    const int bx = blockIdx.x * 32;   // h tile for output
    const int by = blockIdx.y * 32;   // w tile for output
    const int tx = threadIdx.x;
    const int ty = threadIdx.y;       // 32 x 8
    const float g = *gamma;

    // tile[a][b] = outT slice [w=by+a][h=bx+b]  (coalesced read)
#pragma unroll
    for (int i = 0; i < 32; i += 8)
        tile[ty + i][tx] = outT[base + (long)(by + ty + i) * SDIM + bx + tx];
    __syncthreads();

    // output at h = bx+ty+i, w = by+tx  -> needs outT[w][h] = tile[tx][ty+i]
#pragma unroll
    for (int i = 0; i < 32; i += 8) {
        long idx = base + (long)(bx + ty + i) * SDIM + by + tx;
        outS[idx] = g * (outV[idx] + tile[tx][ty + i]);
    }
}

// ---------------- launch ----------------
extern "C" void kernel_launch(void* const* d_in, const int* in_sizes, int n_in,
                              void* d_out, int out_size)
{
    const float* x      = (const float*)d_in[0];
    const float* qkv_w  = (const float*)d_in[1];
    const float* qkv_b  = (const float*)d_in[2];
    const float* out_w  = (const float*)d_in[3];
    const float* out_b  = (const float*)d_in[4];
    const float* gamma  = (const float*)d_in[5];
    float* out = (float*)d_out;
    (void)in_sizes; (void)n_in; (void)out_size;

    float *qkvp, *qkvTp, *outTp, *outVp, *outSp;
    cudaGetSymbolAddress((void**)&qkvp,  g_qkv);
    cudaGetSymbolAddress((void**)&qkvTp, g_qkvT);
    cudaGetSymbolAddress((void**)&outTp, g_outT);
    cudaGetSymbolAddress((void**)&outVp, g_outV);
    cudaGetSymbolAddress((void**)&outSp, g_outS);

    const size_t ATTN_SMEM = (size_t)(2 * 64 * 132 + 64 * 65) * sizeof(float); // 84224 B
    cudaFuncSetAttribute(attn_kernel, cudaFuncAttributeMaxDynamicSharedMemorySize, (int)ATTN_SMEM);

    // 1) qkv = qkv_w @ x + qkv_b          [8][192][h][w]
    gemm_bias_res<<<dim3(128, 3, 8), 256>>>(qkv_w, x, qkvp, qkv_b, nullptr, 192, 512);
    // 2) qkvT[b][ch][w][h]
    transpose_hw<<<dim3(4, 4, 8 * 192), dim3(32, 8)>>>(qkvp, qkvTp);
    // 3) horizontal branch (fixed w, contract over h) -> outT[b][c][w][h]
    attn_kernel<<<dim3(128, 8), 256, ATTN_SMEM>>>(qkvTp, outTp);
    // 4) vertical branch (fixed h, contract over w) -> outV[b][c][h][w]
    attn_kernel<<<dim3(128, 8), 256, ATTN_SMEM>>>(qkvp, outVp);
    // 5) outS = gamma * (outV + outT^T)
    combine_kernel<<<dim3(4, 4, 8 * 64), dim3(32, 8)>>>(outVp, outTp, gamma, outSp);
    // 6) out = out_w @ outS + out_b + x
    gemm_bias_res<<<dim3(128, 8, 8), 256>>>(out_w, outSp, out, out_b, x, 512, 64);
}

// round 3
// speedup vs baseline: 2.3766x; 2.3766x over previous
#include <cuda_runtime.h>
#include <cuda_bf16.h>
#include <math.h>
#include <stdint.h>

#define HW 16384   // 128*128
#define SDIM 128

// ================= scratch =================
__device__ float g_qkv [8L * 192 * HW];   // [b][192][s]
__device__ float g_qkvT[8L * 192 * HW];   // [b][192][w][h]
__device__ float g_outT[8L * 64 * HW];    // horizontal branch, [b][c][w][h]
__device__ float g_outV[8L * 64 * HW];    // vertical branch,   [b][c][h][w]
__device__ __nv_bfloat16 g_sh[8L * 64 * HW];  // gamma*(h+v) bf16 hi, [b][c][s]
__device__ __nv_bfloat16 g_sl[8L * 64 * HW];  // bf16 lo
__device__ __nv_bfloat16 g_wq_hi[192 * 512], g_wq_lo[192 * 512];
__device__ __nv_bfloat16 g_wo_hi[512 * 64],  g_wo_lo[512 * 64];

// ================= mma helpers =================
__device__ __forceinline__ uint32_t smem_u32(const void* p) {
    uint32_t a;
    asm("{ .reg .u64 t; cvta.to.shared.u64 t, %1; cvt.u32.u64 %0, t; }" : "=r"(a) : "l"(p));
    return a;
}
__device__ __forceinline__ void ldsm4(uint32_t r[4], uint32_t a) {
    asm volatile("ldmatrix.sync.aligned.m8n8.x4.shared.b16 {%0,%1,%2,%3}, [%4];"
        : "=r"(r[0]), "=r"(r[1]), "=r"(r[2]), "=r"(r[3]) : "r"(a));
}
__device__ __forceinline__ void ldsm4t(uint32_t r[4], uint32_t a) {
    asm volatile("ldmatrix.sync.aligned.m8n8.x4.trans.shared.b16 {%0,%1,%2,%3}, [%4];"
        : "=r"(r[0]), "=r"(r[1]), "=r"(r[2]), "=r"(r[3]) : "r"(a));
}
__device__ __forceinline__ void mma16816(float c[4], const uint32_t a[4], const uint32_t b[2]) {
    asm volatile("mma.sync.aligned.m16n8k16.row.col.f32.bf16.bf16.f32 "
        "{%0,%1,%2,%3}, {%4,%5,%6,%7}, {%8,%9}, {%0,%1,%2,%3};"
        : "+f"(c[0]), "+f"(c[1]), "+f"(c[2]), "+f"(c[3])
        : "r"(a[0]), "r"(a[1]), "r"(a[2]), "r"(a[3]), "r"(b[0]), "r"(b[1]));
}
__device__ __forceinline__ void cp16(uint32_t d, const void* s) {
    asm volatile("cp.async.ca.shared.global [%0], [%1], 16;" :: "r"(d), "l"(s));
}
#define CP_COMMIT() asm volatile("cp.async.commit_group;" ::: "memory")
#define CP_WAIT0()  asm volatile("cp.async.wait_group 0;" ::: "memory")

__device__ __forceinline__ uint32_t pk(__nv_bfloat16 a, __nv_bfloat16 b) {
    __nv_bfloat162 t; t.x = a; t.y = b;
    return *reinterpret_cast<uint32_t*>(&t);
}

// ================= weight split =================
__global__ __launch_bounds__(256) void split_mat(const float* __restrict__ src,
                                                 __nv_bfloat16* __restrict__ hi,
                                                 __nv_bfloat16* __restrict__ lo, int n)
{
    int i = blockIdx.x * 256 + threadIdx.x;
    if (i < n) {
        float v = src[i];
        __nv_bfloat16 h = __float2bfloat16_rn(v);
        hi[i] = h;
        lo[i] = __float2bfloat16_rn(v - __bfloat162float(h));
    }
}

// ================= GEMM1: qkv[b][o][s] = Wq[o,:] . x[b][:,s] + bias, bf16x3 HMMA =================
// A = Wq hi/lo (192 x 512, K-major). B = x chunk converted in-kernel to bf16 [c][s].
// block: all 192 o x 128 s; K in 16 chunks of 32; double-buffered smem.
#define G1_WH 0
#define G1_WL 7680
#define G1_XH 15360
#define G1_XL 19712
#define G1_BUF 24064                 // bf16 elems per buffer
#define G1_SMEM (2 * G1_BUF * 2)     // 96256 bytes

__global__ __launch_bounds__(256) void gemm1_hmma(
    const __nv_bfloat16* __restrict__ Wh, const __nv_bfloat16* __restrict__ Wl,
    const float* __restrict__ x, const float* __restrict__ bias,
    float* __restrict__ outp)
{
    extern __shared__ __nv_bfloat16 sm[];
    const uint32_t sb = smem_u32(sm);
    const int tid = threadIdx.x;
    const int b = blockIdx.y;
    const int s0 = blockIdx.x * 128;
    const float* xb = x + (long)b * 512 * HW;

    const int warp = tid >> 5, lane = tid & 31;
    const int obase = (warp >> 1) * 48;   // 3 m16 tiles per warp
    const int sbase = (warp & 1) * 64;    // 8 n8 tiles per warp

    float acc[3][8][4];
#pragma unroll
    for (int m = 0; m < 3; m++)
#pragma unroll
        for (int n = 0; n < 8; n++)
#pragma unroll
            for (int q = 0; q < 4; q++) acc[m][n][q] = 0.f;

    float4 xr[4];

    // ---- prologue: chunk 0 into buf 0 ----
#pragma unroll
    for (int i = 0; i < 3; i++) {
        int fi = tid + i * 256;
        int row = fi >> 2, g = fi & 3;
        cp16(sb + (G1_WH + row * 40 + g * 8) * 2, Wh + row * 512 + g * 8);
        cp16(sb + (G1_WL + row * 40 + g * 8) * 2, Wl + row * 512 + g * 8);
    }
    CP_COMMIT();
#pragma unroll
    for (int i = 0; i < 4; i++) {
        int fi = tid + i * 256;
        int row = fi >> 5, c4 = (fi & 31) * 4;
        xr[i] = *(const float4*)&xb[(long)row * HW + s0 + c4];
    }
#pragma unroll
    for (int i = 0; i < 4; i++) {
        int fi = tid + i * 256;
        int row = fi >> 5, c4 = (fi & 31) * 4;
        float4 v = xr[i];
        __nv_bfloat16 h0 = __float2bfloat16_rn(v.x), h1 = __float2bfloat16_rn(v.y);
        __nv_bfloat16 h2 = __float2bfloat16_rn(v.z), h3 = __float2bfloat16_rn(v.w);
        __nv_bfloat16 l0 = __float2bfloat16_rn(v.x - __bfloat162float(h0));
        __nv_bfloat16 l1 = __float2bfloat16_rn(v.y - __bfloat162float(h1));
        __nv_bfloat16 l2 = __float2bfloat16_rn(v.z - __bfloat162float(h2));
        __nv_bfloat16 l3 = __float2bfloat16_rn(v.w - __bfloat162float(h3));
        *(uint2*)&sm[G1_XH + row * 136 + c4] = make_uint2(pk(h0, h1), pk(h2, h3));
        *(uint2*)&sm[G1_XL + row * 136 + c4] = make_uint2(pk(l0, l1), pk(l2, l3));
    }
    CP_WAIT0();
    __syncthreads();

    for (int ch = 0; ch < 16; ch++) {
        const int cur = ch & 1, nxt = cur ^ 1;
        if (ch < 15) {
            const int c0n = (ch + 1) * 32;
#pragma unroll
            for (int i = 0; i < 3; i++) {
                int fi = tid + i * 256;
                int row = fi >> 2, g = fi & 3;
                cp16(sb + (nxt * G1_BUF + G1_WH + row * 40 + g * 8) * 2, Wh + row * 512 + c0n + g * 8);
                cp16(sb + (nxt * G1_BUF + G1_WL + row * 40 + g * 8) * 2, Wl + row * 512 + c0n + g * 8);
            }
            CP_COMMIT();
#pragma unroll
            for (int i = 0; i < 4; i++) {
                int fi = tid + i * 256;
                int row = fi >> 5, c4 = (fi & 31) * 4;
                xr[i] = *(const float4*)&xb[(long)(c0n + row) * HW + s0 + c4];
            }
        }
        // ---- compute chunk ch (2 k16 steps) ----
        const uint32_t wb = sb + (cur * G1_BUF) * 2;
#pragma unroll
        for (int k0 = 0; k0 < 32; k0 += 16) {
            uint32_t Ah[3][4], Al[3][4], B[4][4];
            const int arow = (lane & 15);
            const int acol = k0 + ((lane >> 4) << 3);
#pragma unroll
            for (int m = 0; m < 3; m++) {
                ldsm4(Ah[m], wb + (G1_WH + (obase + m * 16 + arow) * 40 + acol) * 2);
                ldsm4(Al[m], wb + (G1_WL + (obase + m * 16 + arow) * 40 + acol) * 2);
            }
            const int krow = k0 + (lane & 15);
            const int soff = ((lane >> 4) << 3);
#pragma unroll
            for (int j = 0; j < 4; j++)
                ldsm4t(B[j], wb + (G1_XH + krow * 136 + sbase + j * 16 + soff) * 2);
#pragma unroll
            for (int m = 0; m < 3; m++)
#pragma unroll
                for (int j = 0; j < 4; j++) {
                    mma16816(acc[m][2 * j],     Ah[m], &B[j][0]);
                    mma16816(acc[m][2 * j + 1], Ah[m], &B[j][2]);
                }
#pragma unroll
            for (int m = 0; m < 3; m++)
#pragma unroll
                for (int j = 0; j < 4; j++) {
                    mma16816(acc[m][2 * j],     Al[m], &B[j][0]);
                    mma16816(acc[m][2 * j + 1], Al[m], &B[j][2]);
                }
#pragma unroll
            for (int j = 0; j < 4; j++)
                ldsm4t(B[j], wb + (G1_XL + krow * 136 + sbase + j * 16 + soff) * 2);
#pragma unroll
            for (int m = 0; m < 3; m++)
#pragma unroll
                for (int j = 0; j < 4; j++) {
                    mma16816(acc[m][2 * j],     Ah[m], &B[j][0]);
                    mma16816(acc[m][2 * j + 1], Ah[m], &B[j][2]);
                }
        }
        if (ch < 15) {
#pragma unroll
            for (int i = 0; i < 4; i++) {
                int fi = tid + i * 256;
                int row = fi >> 5, c4 = (fi & 31) * 4;
                float4 v = xr[i];
                __nv_bfloat16 h0 = __float2bfloat16_rn(v.x), h1 = __float2bfloat16_rn(v.y);
                __nv_bfloat16 h2 = __float2bfloat16_rn(v.z), h3 = __float2bfloat16_rn(v.w);
                __nv_bfloat16 l0 = __float2bfloat16_rn(v.x - __bfloat162float(h0));
                __nv_bfloat16 l1 = __float2bfloat16_rn(v.y - __bfloat162float(h1));
                __nv_bfloat16 l2 = __float2bfloat16_rn(v.z - __bfloat162float(h2));
                __nv_bfloat16 l3 = __float2bfloat16_rn(v.w - __bfloat162float(h3));
                *(uint2*)&sm[nxt * G1_BUF + G1_XH + row * 136 + c4] = make_uint2(pk(h0, h1), pk(h2, h3));
                *(uint2*)&sm[nxt * G1_BUF + G1_XL + row * 136 + c4] = make_uint2(pk(l0, l1), pk(l2, l3));
            }
        }
        CP_WAIT0();
        __syncthreads();
    }

    // ---- epilogue: C[o][s] + bias ----
    const int g = lane >> 2, t = lane & 3;
    const long ob = (long)b * 192 * HW;
#pragma unroll
    for (int m = 0; m < 3; m++) {
        int o = obase + m * 16 + g;
        float b0 = bias[o], b1 = bias[o + 8];
#pragma unroll
        for (int n = 0; n < 8; n++) {
            int s = s0 + sbase + n * 8 + 2 * t;
            float2 v0 = make_float2(acc[m][n][0] + b0, acc[m][n][1] + b0);
            float2 v1 = make_float2(acc[m][n][2] + b1, acc[m][n][3] + b1);
            *(float2*)&outp[ob + (long)o * HW + s] = v0;
            *(float2*)&outp[ob + (long)(o + 8) * HW + s] = v1;
        }
    }
}

// ================= GEMM2: out = Wo @ S + bias + x, bf16x3 HMMA =================
// A = Wo hi/lo (512 x 64). B = S hi/lo [c][s] (from combine). K = 64 single chunk.
#define G2_AH 0
#define G2_AL 9216
#define G2_SH 18432
#define G2_SL 27136
#define G2_SMEM (35840 * 2)   // 71680 bytes

__global__ __launch_bounds__(256) void gemm2_hmma(
    const __nv_bfloat16* __restrict__ Wh, const __nv_bfloat16* __restrict__ Wl,
    const __nv_bfloat16* __restrict__ Sh, const __nv_bfloat16* __restrict__ Sl,
    const float* __restrict__ bias, const float* __restrict__ resid,
    float* __restrict__ outp)
{
    extern __shared__ __nv_bfloat16 sm[];
    const uint32_t sb = smem_u32(sm);
    const int tid = threadIdx.x;
    const int b = blockIdx.z;
    const int o0 = blockIdx.y * 128;
    const int s0 = blockIdx.x * 128;

    // stage Wo tile [128][64] pitch 72, S [64][128] pitch 136
#pragma unroll
    for (int i = 0; i < 4; i++) {
        int fi = tid + i * 256;
        int row = fi >> 3, gq = fi & 7;
        *(uint4*)&sm[G2_AH + row * 72 + gq * 8] = *(const uint4*)&Wh[(o0 + row) * 64 + gq * 8];
        *(uint4*)&sm[G2_AL + row * 72 + gq * 8] = *(const uint4*)&Wl[(o0 + row) * 64 + gq * 8];
    }
#pragma unroll
    for (int i = 0; i < 4; i++) {
        int fi = tid + i * 256;
        int row = fi >> 4, gq = fi & 15;
        *(uint4*)&sm[G2_SH + row * 136 + gq * 8] = *(const uint4*)&Sh[((long)b * 64 + row) * HW + s0 + gq * 8];
        *(uint4*)&sm[G2_SL + row * 136 + gq * 8] = *(const uint4*)&Sl[((long)b * 64 + row) * HW + s0 + gq * 8];
    }
    __syncthreads();

    const int warp = tid >> 5, lane = tid & 31;
    const int obase = (warp >> 1) * 32;   // 2 m16
    const int sbase = (warp & 1) * 64;    // 8 n8

    float acc[2][8][4];
#pragma unroll
    for (int m = 0; m < 2; m++)
#pragma unroll
        for (int n = 0; n < 8; n++)
#pragma unroll
            for (int q = 0; q < 4; q++) acc[m][n][q] = 0.f;

#pragma unroll
    for (int k0 = 0; k0 < 64; k0 += 16) {
        uint32_t Ah[2][4], Al[2][4], B[4][4];
        const int arow = (lane & 15);
        const int acol = k0 + ((lane >> 4) << 3);
#pragma unroll
        for (int m = 0; m < 2; m++) {
            ldsm4(Ah[m], sb + (G2_AH + (obase + m * 16 + arow) * 72 + acol) * 2);
            ldsm4(Al[m], sb + (G2_AL + (obase + m * 16 + arow) * 72 + acol) * 2);
        }
        const int krow = k0 + (lane & 15);
        const int soff = ((lane >> 4) << 3);
#pragma unroll
        for (int j = 0; j < 4; j++)
            ldsm4t(B[j], sb + (G2_SH + krow * 136 + sbase + j * 16 + soff) * 2);
#pragma unroll
        for (int m = 0; m < 2; m++)
#pragma unroll
            for (int j = 0; j < 4; j++) {
                mma16816(acc[m][2 * j],     Ah[m], &B[j][0]);
                mma16816(acc[m][2 * j + 1], Ah[m], &B[j][2]);
            }
#pragma unroll
        for (int m = 0; m < 2; m++)
#pragma unroll
            for (int j = 0; j < 4; j++) {
                mma16816(acc[m][2 * j],     Al[m], &B[j][0]);
                mma16816(acc[m][2 * j + 1], Al[m], &B[j][2]);
            }
#pragma unroll
        for (int j = 0; j < 4; j++)
            ldsm4t(B[j], sb + (G2_SL + krow * 136 + sbase + j * 16 + soff) * 2);
#pragma unroll
        for (int m = 0; m < 2; m++)
#pragma unroll
            for (int j = 0; j < 4; j++) {
                mma16816(acc[m][2 * j],     Ah[m], &B[j][0]);
                mma16816(acc[m][2 * j + 1], Ah[m], &B[j][2]);
            }
    }

    // epilogue: + bias + resid
    const int g = lane >> 2, t = lane & 3;
#pragma unroll
    for (int m = 0; m < 2; m++) {
        int o = o0 + obase + m * 16 + g;
        float b0 = bias[o], b1 = bias[o + 8];
#pragma unroll
        for (int n = 0; n < 8; n++) {
            int s = s0 + sbase + n * 8 + 2 * t;
            long i0 = ((long)b * 512 + o) * HW + s;
            long i1 = ((long)b * 512 + o + 8) * HW + s;
            float2 r0 = *(const float2*)&resid[i0];
            float2 r1 = *(const float2*)&resid[i1];
            float2 v0 = make_float2(acc[m][n][0] + b0 + r0.x, acc[m][n][1] + b0 + r0.y);
            float2 v1 = make_float2(acc[m][n][2] + b1 + r1.x, acc[m][n][3] + b1 + r1.y);
            *(float2*)&outp[i0] = v0;
            *(float2*)&outp[i1] = v1;
        }
    }
}

// ================= 128x128 HW-transpose per slice =================
__global__ __launch_bounds__(256) void transpose_hw(const float* __restrict__ in,
                                                    float* __restrict__ out)
{
    __shared__ float tile[32][33];
    const long base = (long)blockIdx.z * HW;
    const int bx = blockIdx.x * 32;
    const int by = blockIdx.y * 32;
    const int tx = threadIdx.x;
    const int ty = threadIdx.y;   // 32 x 8
#pragma unroll
    for (int i = 0; i < 32; i += 8)
        tile[ty + i][tx] = in[base + (long)(by + ty + i) * SDIM + bx + tx];
    __syncthreads();
#pragma unroll
    for (int i = 0; i < 32; i += 8)
        out[base + (long)(bx + ty + i) * SDIM + by + tx] = tile[tx][ty + i];
}

// ================= attention branch =================
__global__ __launch_bounds__(256) void attn_kernel(const float* __restrict__ qkv,
                                                   float* __restrict__ outp)
{
    extern __shared__ float smf[];
    float* Qs = smf;                 // [64][132]  (later reused for V)
    float* Ks = smf + 64 * 132;      // [64][132]
    float* Es = smf + 2 * 64 * 132;  // [64][65]

    const int b = blockIdx.y;
    const int s = blockIdx.x;
    const int tid = threadIdx.x;
    const long base = (long)b * 192 * HW + (long)s * SDIM;

#pragma unroll
    for (int t = 0; t < 8; t++) {
        int fi = tid + t * 256;
        int row = fi >> 5;
        int c4 = (fi & 31) * 4;
        *(float4*)&Qs[row * 132 + c4] = *(const float4*)&qkv[base + (long)row * HW + c4];
        *(float4*)&Ks[row * 132 + c4] = *(const float4*)&qkv[base + (long)(row + 64) * HW + c4];
    }
    __syncthreads();

    {
        const int ti = tid & 15;
        const int tj = tid >> 4;
        float acc[4][4];
#pragma unroll
        for (int i = 0; i < 4; i++)
#pragma unroll
            for (int j = 0; j < 4; j++) acc[i][j] = 0.f;

        for (int h = 0; h < 128; h += 4) {
            float4 qv[4], kv[4];
#pragma unroll
            for (int i = 0; i < 4; i++) qv[i] = *(float4*)&Qs[(ti + 16 * i) * 132 + h];
#pragma unroll
            for (int j = 0; j < 4; j++) kv[j] = *(float4*)&Ks[(tj + 16 * j) * 132 + h];
#pragma unroll
            for (int i = 0; i < 4; i++)
#pragma unroll
                for (int j = 0; j < 4; j++) {
                    acc[i][j] = fmaf(qv[i].x, kv[j].x, acc[i][j]);
                    acc[i][j] = fmaf(qv[i].y, kv[j].y, acc[i][j]);
                    acc[i][j] = fmaf(qv[i].z, kv[j].z, acc[i][j]);
                    acc[i][j] = fmaf(qv[i].w, kv[j].w, acc[i][j]);
                }
        }
#pragma unroll
        for (int i = 0; i < 4; i++)
#pragma unroll
            for (int j = 0; j < 4; j++)
                Es[(ti + 16 * i) * 65 + tj + 16 * j] = acc[i][j];
    }
    __syncthreads();

#pragma unroll
    for (int t = 0; t < 8; t++) {
        int fi = tid + t * 256;
        int row = fi >> 5;
        int c4 = (fi & 31) * 4;
        *(float4*)&Qs[row * 132 + c4] = *(const float4*)&qkv[base + (long)(row + 128) * HW + c4];
    }
    if (tid < 64) {
        float* row = &Es[tid * 65];
        float m = -INFINITY;
#pragma unroll
        for (int j = 0; j < 64; j++) m = fmaxf(m, row[j]);
        float ssum = 0.f;
#pragma unroll
        for (int j = 0; j < 64; j++) { float e = __expf(row[j] - m); row[j] = e; ssum += e; }
        float inv = 1.f / ssum;
#pragma unroll
        for (int j = 0; j < 64; j++) row[j] *= inv;
    }
    __syncthreads();

    {
        const int warp = tid >> 5;
        const int lane = tid & 31;
        const int i0 = warp * 8;
        float o[8][4];
#pragma unroll
        for (int r = 0; r < 8; r++)
#pragma unroll
            for (int hh = 0; hh < 4; hh++) o[r][hh] = 0.f;

        for (int j = 0; j < 64; j++) {
            float a[8];
#pragma unroll
            for (int r = 0; r < 8; r++) a[r] = Es[(i0 + r) * 65 + j];
            float v[4];
#pragma unroll
            for (int hh = 0; hh < 4; hh++) v[hh] = Qs[j * 132 + hh * 32 + lane];
#pragma unroll
            for (int r = 0; r < 8; r++)
#pragma unroll
                for (int hh = 0; hh < 4; hh++)
                    o[r][hh] = fmaf(a[r], v[hh], o[r][hh]);
        }

        const long obase = (long)b * 64 * HW + (long)s * SDIM;
#pragma unroll
        for (int r = 0; r < 8; r++)
#pragma unroll
            for (int hh = 0; hh < 4; hh++)
                outp[obase + (long)(i0 + r) * HW + hh * 32 + lane] = o[r][hh];
    }
}

// ================= combine + bf16 split (fused) =================
__global__ __launch_bounds__(256) void combine_split(const float* __restrict__ outV,
                                                     const float* __restrict__ outT,
                                                     const float* __restrict__ gamma,
                                                     __nv_bfloat16* __restrict__ Sh,
                                                     __nv_bfloat16* __restrict__ Sl)
{
    __shared__ float tile[32][33];
    const long base = (long)blockIdx.z * HW;
    const int bx = blockIdx.x * 32;
    const int by = blockIdx.y * 32;
    const int tx = threadIdx.x;
    const int ty = threadIdx.y;
    const float g = *gamma;

#pragma unroll
    for (int i = 0; i < 32; i += 8)
        tile[ty + i][tx] = outT[base + (long)(by + ty + i) * SDIM + bx + tx];
    __syncthreads();
#pragma unroll
    for (int i = 0; i < 32; i += 8) {
        long idx = base + (long)(bx + ty + i) * SDIM + by + tx;
        float v = g * (outV[idx] + tile[tx][ty + i]);
        __nv_bfloat16 h = __float2bfloat16_rn(v);
        Sh[idx] = h;
        Sl[idx] = __float2bfloat16_rn(v - __bfloat162float(h));
    }
}

// ================= launch =================
extern "C" void kernel_launch(void* const* d_in, const int* in_sizes, int n_in,
                              void* d_out, int out_size)
{
    const float* x      = (const float*)d_in[0];
    const float* qkv_w  = (const float*)d_in[1];
    const float* qkv_b  = (const float*)d_in[2];
    const float* out_w  = (const float*)d_in[3];
    const float* out_b  = (const float*)d_in[4];
    const float* gamma  = (const float*)d_in[5];
    float* out = (float*)d_out;
    (void)in_sizes; (void)n_in; (void)out_size;

    float *qkvp, *qkvTp, *outTp, *outVp;
    __nv_bfloat16 *wqh, *wql, *woh, *wol, *shp, *slp;
    cudaGetSymbolAddress((void**)&qkvp,  g_qkv);
    cudaGetSymbolAddress((void**)&qkvTp, g_qkvT);
    cudaGetSymbolAddress((void**)&outTp, g_outT);
    cudaGetSymbolAddress((void**)&outVp, g_outV);
    cudaGetSymbolAddress((void**)&wqh, g_wq_hi);
    cudaGetSymbolAddress((void**)&wql, g_wq_lo);
    cudaGetSymbolAddress((void**)&woh, g_wo_hi);
    cudaGetSymbolAddress((void**)&wol, g_wo_lo);
    cudaGetSymbolAddress((void**)&shp, g_sh);
    cudaGetSymbolAddress((void**)&slp, g_sl);

    const size_t ATTN_SMEM = (size_t)(2 * 64 * 132 + 64 * 65) * sizeof(float);
    cudaFuncSetAttribute(attn_kernel, cudaFuncAttributeMaxDynamicSharedMemorySize, (int)ATTN_SMEM);
    cudaFuncSetAttribute(gemm1_hmma, cudaFuncAttributeMaxDynamicSharedMemorySize, G1_SMEM);
    cudaFuncSetAttribute(gemm2_hmma, cudaFuncAttributeMaxDynamicSharedMemorySize, G2_SMEM);

    // 0) weight splits
    split_mat<<<(192 * 512 + 255) / 256, 256>>>(qkv_w, wqh, wql, 192 * 512);
    split_mat<<<(512 * 64 + 255) / 256, 256>>>(out_w, woh, wol, 512 * 64);
    // 1) qkv
    gemm1_hmma<<<dim3(128, 8), 256, G1_SMEM>>>(wqh, wql, x, qkv_b, qkvp);
    // 2) transpose for horizontal branch
    transpose_hw<<<dim3(4, 4, 8 * 192), dim3(32, 8)>>>(qkvp, qkvTp);
    // 3,4) attention branches
    attn_kernel<<<dim3(128, 8), 256, ATTN_SMEM>>>(qkvTp, outTp);
    attn_kernel<<<dim3(128, 8), 256, ATTN_SMEM>>>(qkvp, outVp);
    // 5) combine + split to bf16 [c][s]
    combine_split<<<dim3(4, 4, 8 * 64), dim3(32, 8)>>>(outVp, outTp, gamma, shp, slp);
    // 6) out projection + bias + residual
    gemm2_hmma<<<dim3(128, 4, 8), 256, G2_SMEM>>>(woh, wol, shp, slp, out_b, x, out);
}

// round 4
// speedup vs baseline: 2.6343x; 1.1084x over previous
#include <cuda_runtime.h>
#include <cuda_bf16.h>
#include <math.h>
#include <stdint.h>

#define HW 16384   // 128*128
#define SDIM 128

// ================= scratch =================
__device__ float g_qkv [8L * 192 * HW];   // [b][192][s]
__device__ float g_qkvT[8L * 192 * HW];   // [b][192][w][h]
__device__ float g_outT[8L * 64 * HW];    // horizontal branch, [b][c][w][h]
__device__ float g_outV[8L * 64 * HW];    // vertical branch,   [b][c][h][w]
__device__ __nv_bfloat16 g_sh[8L * 64 * HW];  // gamma*(h+v) bf16 hi, [b][c][s]
__device__ __nv_bfloat16 g_sl[8L * 64 * HW];  // bf16 lo
__device__ __nv_bfloat16 g_wq_hi[192 * 512], g_wq_lo[192 * 512];
__device__ __nv_bfloat16 g_wo_hi[512 * 64],  g_wo_lo[512 * 64];

// ================= mma helpers =================
__device__ __forceinline__ uint32_t smem_u32(const void* p) {
    uint32_t a;
    asm("{ .reg .u64 t; cvta.to.shared.u64 t, %1; cvt.u32.u64 %0, t; }" : "=r"(a) : "l"(p));
    return a;
}
__device__ __forceinline__ void ldsm4(uint32_t r[4], uint32_t a) {
    asm volatile("ldmatrix.sync.aligned.m8n8.x4.shared.b16 {%0,%1,%2,%3}, [%4];"
        : "=r"(r[0]), "=r"(r[1]), "=r"(r[2]), "=r"(r[3]) : "r"(a));
}
__device__ __forceinline__ void ldsm4t(uint32_t r[4], uint32_t a) {
    asm volatile("ldmatrix.sync.aligned.m8n8.x4.trans.shared.b16 {%0,%1,%2,%3}, [%4];"
        : "=r"(r[0]), "=r"(r[1]), "=r"(r[2]), "=r"(r[3]) : "r"(a));
}
// B-operand fragments for row.col mma from ROW-MAJOR [n][k] storage.
// Yields {r0,r1} = b-frag for n-tile [n0..n0+7], {r2,r3} for [n0+8..n0+15].
__device__ __forceinline__ void ldsm4_bnk(uint32_t r[4], uint32_t base_bytes, int pitch_bytes) {
    int lane = threadIdx.x & 31;
    int rr = lane & 7, grp = lane >> 3;
    int n = rr + ((grp & 2) ? 8 : 0);
    int k = (grp & 1) ? 8 : 0;
    ldsm4(r, base_bytes + n * pitch_bytes + k * 2);
}
__device__ __forceinline__ void mma16816(float c[4], const uint32_t a[4], const uint32_t b[2]) {
    asm volatile("mma.sync.aligned.m16n8k16.row.col.f32.bf16.bf16.f32 "
        "{%0,%1,%2,%3}, {%4,%5,%6,%7}, {%8,%9}, {%0,%1,%2,%3};"
        : "+f"(c[0]), "+f"(c[1]), "+f"(c[2]), "+f"(c[3])
        : "r"(a[0]), "r"(a[1]), "r"(a[2]), "r"(a[3]), "r"(b[0]), "r"(b[1]));
}
__device__ __forceinline__ void cp16(uint32_t d, const void* s) {
    asm volatile("cp.async.ca.shared.global [%0], [%1], 16;" :: "r"(d), "l"(s));
}
#define CP_COMMIT() asm volatile("cp.async.commit_group;" ::: "memory")
#define CP_WAIT0()  asm volatile("cp.async.wait_group 0;" ::: "memory")

__device__ __forceinline__ uint32_t pk(__nv_bfloat16 a, __nv_bfloat16 b) {
    __nv_bfloat162 t; t.x = a; t.y = b;
    return *reinterpret_cast<uint32_t*>(&t);
}
__device__ __forceinline__ void split4(float4 v, uint2& hi, uint2& lo) {
    __nv_bfloat16 h0 = __float2bfloat16_rn(v.x), h1 = __float2bfloat16_rn(v.y);
    __nv_bfloat16 h2 = __float2bfloat16_rn(v.z), h3 = __float2bfloat16_rn(v.w);
    __nv_bfloat16 l0 = __float2bfloat16_rn(v.x - __bfloat162float(h0));
    __nv_bfloat16 l1 = __float2bfloat16_rn(v.y - __bfloat162float(h1));
    __nv_bfloat16 l2 = __float2bfloat16_rn(v.z - __bfloat162float(h2));
    __nv_bfloat16 l3 = __float2bfloat16_rn(v.w - __bfloat162float(h3));
    hi = make_uint2(pk(h0, h1), pk(h2, h3));
    lo = make_uint2(pk(l0, l1), pk(l2, l3));
}

// ================= weight split =================
__global__ __launch_bounds__(256) void split_mat(const float* __restrict__ src,
                                                 __nv_bfloat16* __restrict__ hi,
                                                 __nv_bfloat16* __restrict__ lo, int n)
{
    int i = blockIdx.x * 256 + threadIdx.x;
    if (i < n) {
        float v = src[i];
        __nv_bfloat16 h = __float2bfloat16_rn(v);
        hi[i] = h;
        lo[i] = __float2bfloat16_rn(v - __bfloat162float(h));
    }
}

// ================= GEMM1 (unchanged from R3) =================
#define G1_WH 0
#define G1_WL 7680
#define G1_XH 15360
#define G1_XL 19712
#define G1_BUF 24064
#define G1_SMEM (2 * G1_BUF * 2)

__global__ __launch_bounds__(256) void gemm1_hmma(
    const __nv_bfloat16* __restrict__ Wh, const __nv_bfloat16* __restrict__ Wl,
    const float* __restrict__ x, const float* __restrict__ bias,
    float* __restrict__ outp)
{
    extern __shared__ __nv_bfloat16 sm[];
    const uint32_t sb = smem_u32(sm);
    const int tid = threadIdx.x;
    const int b = blockIdx.y;
    const int s0 = blockIdx.x * 128;
    const float* xb = x + (long)b * 512 * HW;

    const int warp = tid >> 5, lane = tid & 31;
    const int obase = (warp >> 1) * 48;
    const int sbase = (warp & 1) * 64;

    float acc[3][8][4];
#pragma unroll
    for (int m = 0; m < 3; m++)
#pragma unroll
        for (int n = 0; n < 8; n++)
#pragma unroll
            for (int q = 0; q < 4; q++) acc[m][n][q] = 0.f;

    float4 xr[4];

#pragma unroll
    for (int i = 0; i < 3; i++) {
        int fi = tid + i * 256;
        int row = fi >> 2, g = fi & 3;
        cp16(sb + (G1_WH + row * 40 + g * 8) * 2, Wh + row * 512 + g * 8);
        cp16(sb + (G1_WL + row * 40 + g * 8) * 2, Wl + row * 512 + g * 8);
    }
    CP_COMMIT();
#pragma unroll
    for (int i = 0; i < 4; i++) {
        int fi = tid + i * 256;
        int row = fi >> 5, c4 = (fi & 31) * 4;
        xr[i] = *(const float4*)&xb[(long)row * HW + s0 + c4];
    }
#pragma unroll
    for (int i = 0; i < 4; i++) {
        int fi = tid + i * 256;
        int row = fi >> 5, c4 = (fi & 31) * 4;
        uint2 hi, lo; split4(xr[i], hi, lo);
        *(uint2*)&sm[G1_XH + row * 136 + c4] = hi;
        *(uint2*)&sm[G1_XL + row * 136 + c4] = lo;
    }
    CP_WAIT0();
    __syncthreads();

    for (int ch = 0; ch < 16; ch++) {
        const int cur = ch & 1, nxt = cur ^ 1;
        if (ch < 15) {
            const int c0n = (ch + 1) * 32;
#pragma unroll
            for (int i = 0; i < 3; i++) {
                int fi = tid + i * 256;
                int row = fi >> 2, g = fi & 3;
                cp16(sb + (nxt * G1_BUF + G1_WH + row * 40 + g * 8) * 2, Wh + row * 512 + c0n + g * 8);
                cp16(sb + (nxt * G1_BUF + G1_WL + row * 40 + g * 8) * 2, Wl + row * 512 + c0n + g * 8);
            }
            CP_COMMIT();
#pragma unroll
            for (int i = 0; i < 4; i++) {
                int fi = tid + i * 256;
                int row = fi >> 5, c4 = (fi & 31) * 4;
                xr[i] = *(const float4*)&xb[(long)(c0n + row) * HW + s0 + c4];
            }
        }
        const uint32_t wb = sb + (cur * G1_BUF) * 2;
#pragma unroll
        for (int k0 = 0; k0 < 32; k0 += 16) {
            uint32_t Ah[3][4], Al[3][4], B[4][4];
            const int arow = (lane & 15);
            const int acol = k0 + ((lane >> 4) << 3);
#pragma unroll
            for (int m = 0; m < 3; m++) {
                ldsm4(Ah[m], wb + (G1_WH + (obase + m * 16 + arow) * 40 + acol) * 2);
                ldsm4(Al[m], wb + (G1_WL + (obase + m * 16 + arow) * 40 + acol) * 2);
            }
            const int krow = k0 + (lane & 15);
            const int soff = ((lane >> 4) << 3);
#pragma unroll
            for (int j = 0; j < 4; j++)
                ldsm4t(B[j], wb + (G1_XH + krow * 136 + sbase + j * 16 + soff) * 2);
#pragma unroll
            for (int m = 0; m < 3; m++)
#pragma unroll
                for (int j = 0; j < 4; j++) {
                    mma16816(acc[m][2 * j],     Ah[m], &B[j][0]);
                    mma16816(acc[m][2 * j + 1], Ah[m], &B[j][2]);
                }
#pragma unroll
            for (int m = 0; m < 3; m++)
#pragma unroll
                for (int j = 0; j < 4; j++) {
                    mma16816(acc[m][2 * j],     Al[m], &B[j][0]);
                    mma16816(acc[m][2 * j + 1], Al[m], &B[j][2]);
                }
#pragma unroll
            for (int j = 0; j < 4; j++)
                ldsm4t(B[j], wb + (G1_XL + krow * 136 + sbase + j * 16 + soff) * 2);
#pragma unroll
            for (int m = 0; m < 3; m++)
#pragma unroll
                for (int j = 0; j < 4; j++) {
                    mma16816(acc[m][2 * j],     Ah[m], &B[j][0]);
                    mma16816(acc[m][2 * j + 1], Ah[m], &B[j][2]);
                }
        }
        if (ch < 15) {
#pragma unroll
            for (int i = 0; i < 4; i++) {
                int fi = tid + i * 256;
                int row = fi >> 5, c4 = (fi & 31) * 4;
                uint2 hi, lo; split4(xr[i], hi, lo);
                *(uint2*)&sm[nxt * G1_BUF + G1_XH + row * 136 + c4] = hi;
                *(uint2*)&sm[nxt * G1_BUF + G1_XL + row * 136 + c4] = lo;
            }
        }
        CP_WAIT0();
        __syncthreads();
    }

    const int g = lane >> 2, t = lane & 3;
    const long ob = (long)b * 192 * HW;
#pragma unroll
    for (int m = 0; m < 3; m++) {
        int o = obase + m * 16 + g;
        float b0 = bias[o], b1 = bias[o + 8];
#pragma unroll
        for (int n = 0; n < 8; n++) {
            int s = s0 + sbase + n * 8 + 2 * t;
            float2 v0 = make_float2(acc[m][n][0] + b0, acc[m][n][1] + b0);
            float2 v1 = make_float2(acc[m][n][2] + b1, acc[m][n][3] + b1);
            *(float2*)&outp[ob + (long)o * HW + s] = v0;
            *(float2*)&outp[ob + (long)(o + 8) * HW + s] = v1;
        }
    }
}

// ================= GEMM2 (unchanged from R3) =================
#define G2_AH 0
#define G2_AL 9216
#define G2_SH 18432
#define G2_SL 27136
#define G2_SMEM (35840 * 2)

__global__ __launch_bounds__(256) void gemm2_hmma(
    const __nv_bfloat16* __restrict__ Wh, const __nv_bfloat16* __restrict__ Wl,
    const __nv_bfloat16* __restrict__ Sh, const __nv_bfloat16* __restrict__ Sl,
    const float* __restrict__ bias, const float* __restrict__ resid,
    float* __restrict__ outp)
{
    extern __shared__ __nv_bfloat16 sm[];
    const uint32_t sb = smem_u32(sm);
    const int tid = threadIdx.x;
    const int b = blockIdx.z;
    const int o0 = blockIdx.y * 128;
    const int s0 = blockIdx.x * 128;

#pragma unroll
    for (int i = 0; i < 4; i++) {
        int fi = tid + i * 256;
        int row = fi >> 3, gq = fi & 7;
        *(uint4*)&sm[G2_AH + row * 72 + gq * 8] = *(const uint4*)&Wh[(o0 + row) * 64 + gq * 8];
        *(uint4*)&sm[G2_AL + row * 72 + gq * 8] = *(const uint4*)&Wl[(o0 + row) * 64 + gq * 8];
    }
#pragma unroll
    for (int i = 0; i < 4; i++) {
        int fi = tid + i * 256;
        int row = fi >> 4, gq = fi & 15;
        *(uint4*)&sm[G2_SH + row * 136 + gq * 8] = *(const uint4*)&Sh[((long)b * 64 + row) * HW + s0 + gq * 8];
        *(uint4*)&sm[G2_SL + row * 136 + gq * 8] = *(const uint4*)&Sl[((long)b * 64 + row) * HW + s0 + gq * 8];
    }
    __syncthreads();

    const int warp = tid >> 5, lane = tid & 31;
    const int obase = (warp >> 1) * 32;
    const int sbase = (warp & 1) * 64;

    float acc[2][8][4];
#pragma unroll
    for (int m = 0; m < 2; m++)
#pragma unroll
        for (int n = 0; n < 8; n++)
#pragma unroll
            for (int q = 0; q < 4; q++) acc[m][n][q] = 0.f;

#pragma unroll
    for (int k0 = 0; k0 < 64; k0 += 16) {
        uint32_t Ah[2][4], Al[2][4], B[4][4];
        const int arow = (lane & 15);
        const int acol = k0 + ((lane >> 4) << 3);
#pragma unroll
        for (int m = 0; m < 2; m++) {
            ldsm4(Ah[m], sb + (G2_AH + (obase + m * 16 + arow) * 72 + acol) * 2);
            ldsm4(Al[m], sb + (G2_AL + (obase + m * 16 + arow) * 72 + acol) * 2);
        }
        const int krow = k0 + (lane & 15);
        const int soff = ((lane >> 4) << 3);
#pragma unroll
        for (int j = 0; j < 4; j++)
            ldsm4t(B[j], sb + (G2_SH + krow * 136 + sbase + j * 16 + soff) * 2);
#pragma unroll
        for (int m = 0; m < 2; m++)
#pragma unroll
            for (int j = 0; j < 4; j++) {
                mma16816(acc[m][2 * j],     Ah[m], &B[j][0]);
                mma16816(acc[m][2 * j + 1], Ah[m], &B[j][2]);
            }
#pragma unroll
        for (int m = 0; m < 2; m++)
#pragma unroll
            for (int j = 0; j < 4; j++) {
                mma16816(acc[m][2 * j],     Al[m], &B[j][0]);
                mma16816(acc[m][2 * j + 1], Al[m], &B[j][2]);
            }
#pragma unroll
        for (int j = 0; j < 4; j++)
            ldsm4t(B[j], sb + (G2_SL + krow * 136 + sbase + j * 16 + soff) * 2);
#pragma unroll
        for (int m = 0; m < 2; m++)
#pragma unroll
            for (int j = 0; j < 4; j++) {
                mma16816(acc[m][2 * j],     Ah[m], &B[j][0]);
                mma16816(acc[m][2 * j + 1], Ah[m], &B[j][2]);
            }
    }

    const int g = lane >> 2, t = lane & 3;
#pragma unroll
    for (int m = 0; m < 2; m++) {
        int o = o0 + obase + m * 16 + g;
        float b0 = bias[o], b1 = bias[o + 8];
#pragma unroll
        for (int n = 0; n < 8; n++) {
            int s = s0 + sbase + n * 8 + 2 * t;
            long i0 = ((long)b * 512 + o) * HW + s;
            long i1 = ((long)b * 512 + o + 8) * HW + s;
            float2 r0 = *(const float2*)&resid[i0];
            float2 r1 = *(const float2*)&resid[i1];
            float2 v0 = make_float2(acc[m][n][0] + b0 + r0.x, acc[m][n][1] + b0 + r0.y);
            float2 v1 = make_float2(acc[m][n][2] + b1 + r1.x, acc[m][n][3] + b1 + r1.y);
            *(float2*)&outp[i0] = v0;
            *(float2*)&outp[i1] = v1;
        }
    }
}

// ================= 128x128 HW-transpose per slice =================
__global__ __launch_bounds__(256) void transpose_hw(const float* __restrict__ in,
                                                    float* __restrict__ out)
{
    __shared__ float tile[32][33];
    const long base = (long)blockIdx.z * HW;
    const int bx = blockIdx.x * 32;
    const int by = blockIdx.y * 32;
    const int tx = threadIdx.x;
    const int ty = threadIdx.y;
#pragma unroll
    for (int i = 0; i < 32; i += 8)
        tile[ty + i][tx] = in[base + (long)(by + ty + i) * SDIM + bx + tx];
    __syncthreads();
#pragma unroll
    for (int i = 0; i < 32; i += 8)
        out[base + (long)(bx + ty + i) * SDIM + by + tx] = tile[tx][ty + i];
}

// ================= HMMA attention branch =================
// smem (bf16 elem offsets):
//  QH=0, QL=8704           : Q hi/lo [64][136]   (reused for V after E phase)
//  KH=17408, KL=26112      : K hi/lo [64][136]
//  ES=34816 (fp32 [64][65]): energy / softmax
//  PH=43136, PL=47744      : attn bf16 hi/lo [64][72]
#define AT_QH 0
#define AT_QL 8704
#define AT_KH 17408
#define AT_KL 26112
#define AT_ES 34816
#define AT_PH 43136
#define AT_PL 47744
#define AT_SMEM (52352 * 2)   // 104704 bytes

__global__ __launch_bounds__(256) void attn_hmma(const float* __restrict__ qkv,
                                                 float* __restrict__ outp)
{
    extern __shared__ __nv_bfloat16 sm[];
    const uint32_t sb = smem_u32(sm);
    float* Ef = (float*)(sm + AT_ES);

    const int b = blockIdx.y;
    const int s = blockIdx.x;
    const int tid = threadIdx.x;
    const int warp = tid >> 5, lane = tid & 31;
    const long base = (long)b * 192 * HW + (long)s * SDIM;

    // --- stage Q, K as bf16 hi/lo (natural [c][h] layout) ---
#pragma unroll
    for (int t = 0; t < 8; t++) {
        int fi = tid + t * 256;
        int row = fi >> 5, c4 = (fi & 31) * 4;
        float4 qv = *(const float4*)&qkv[base + (long)row * HW + c4];
        float4 kv = *(const float4*)&qkv[base + (long)(row + 64) * HW + c4];
        uint2 hi, lo;
        split4(qv, hi, lo);
        *(uint2*)&sm[AT_QH + row * 136 + c4] = hi;
        *(uint2*)&sm[AT_QL + row * 136 + c4] = lo;
        split4(kv, hi, lo);
        *(uint2*)&sm[AT_KH + row * 136 + c4] = hi;
        *(uint2*)&sm[AT_KL + row * 136 + c4] = lo;
    }
    __syncthreads();

    // --- E = Q.K^T (bf16x3), E[q][kk], contract over h=128 ---
    {
        const int mw = warp >> 1;            // 4 m16 tiles over q
        const int nb = (warp & 1) * 32;      // 32 kk columns per warp
        float eacc[4][4];
#pragma unroll
        for (int i = 0; i < 4; i++)
#pragma unroll
            for (int q = 0; q < 4; q++) eacc[i][q] = 0.f;

#pragma unroll
        for (int k0 = 0; k0 < 128; k0 += 16) {
            uint32_t Ah[4], Al[4];
            const uint32_t aoff = ((mw * 16 + (lane & 15)) * 136 + k0 + ((lane >> 4) << 3)) * 2;
            ldsm4(Ah, sb + AT_QH * 2 + aoff);
            ldsm4(Al, sb + AT_QL * 2 + aoff);
#pragma unroll
            for (int j = 0; j < 2; j++) {
                uint32_t Bh[4], Bl[4];
                const uint32_t bbase = ((nb + j * 16) * 136 + k0) * 2;
                ldsm4_bnk(Bh, sb + AT_KH * 2 + bbase, 272);
                ldsm4_bnk(Bl, sb + AT_KL * 2 + bbase, 272);
#pragma unroll
                for (int h = 0; h < 2; h++) {
                    mma16816(eacc[j * 2 + h], Ah, &Bh[h * 2]);
                    mma16816(eacc[j * 2 + h], Ah, &Bl[h * 2]);
                    mma16816(eacc[j * 2 + h], Al, &Bh[h * 2]);
                }
            }
        }
        // write E to fp32 smem
        const int g = lane >> 2, t = lane & 3;
#pragma unroll
        for (int j = 0; j < 2; j++)
#pragma unroll
            for (int h = 0; h < 2; h++) {
                int n = nb + j * 16 + h * 8 + 2 * t;
                int tt = j * 2 + h;
                Ef[(mw * 16 + g) * 65 + n]     = eacc[tt][0];
                Ef[(mw * 16 + g) * 65 + n + 1] = eacc[tt][1];
                Ef[(mw * 16 + g + 8) * 65 + n]     = eacc[tt][2];
                Ef[(mw * 16 + g + 8) * 65 + n + 1] = eacc[tt][3];
            }
    }
    __syncthreads();

    // --- stage V into Q's buffers; softmax on E ---
#pragma unroll
    for (int t = 0; t < 8; t++) {
        int fi = tid + t * 256;
        int row = fi >> 5, c4 = (fi & 31) * 4;
        float4 vv = *(const float4*)&qkv[base + (long)(row + 128) * HW + c4];
        uint2 hi, lo; split4(vv, hi, lo);
        *(uint2*)&sm[AT_QH + row * 136 + c4] = hi;
        *(uint2*)&sm[AT_QL + row * 136 + c4] = lo;
    }
    if (tid < 64) {
        float* row = &Ef[tid * 65];
        float m = -INFINITY;
#pragma unroll
        for (int j = 0; j < 64; j++) m = fmaxf(m, row[j]);
        float ssum = 0.f;
#pragma unroll
        for (int j = 0; j < 64; j++) { float e = __expf(row[j] - m); row[j] = e; ssum += e; }
        float inv = 1.f / ssum;
#pragma unroll
        for (int j = 0; j < 64; j++) row[j] *= inv;
    }
    __syncthreads();

    // --- attn fp32 -> bf16 hi/lo [q][j] pitch 72 ---
    {
        int row = tid >> 2;
        int cb = (tid & 3) * 16;
#pragma unroll
        for (int c = 0; c < 16; c += 4) {
            float4 v = make_float4(Ef[row * 65 + cb + c], Ef[row * 65 + cb + c + 1],
                                   Ef[row * 65 + cb + c + 2], Ef[row * 65 + cb + c + 3]);
            uint2 hi, lo; split4(v, hi, lo);
            *(uint2*)&sm[AT_PH + row * 72 + cb + c] = hi;
            *(uint2*)&sm[AT_PL + row * 72 + cb + c] = lo;
        }
    }
    __syncthreads();

    // --- out = P.V (bf16x3), contract over j=64, n = t (128 cols) ---
    {
        const int mw = warp >> 1;            // 4 m16 tiles over q
        const int nb = (warp & 1) * 64;      // 64 t columns per warp
        float acc[8][4];
#pragma unroll
        for (int n = 0; n < 8; n++)
#pragma unroll
            for (int q = 0; q < 4; q++) acc[n][q] = 0.f;

#pragma unroll
        for (int k0 = 0; k0 < 64; k0 += 16) {
            uint32_t Ph[4], Pl[4];
            const uint32_t aoff = ((mw * 16 + (lane & 15)) * 72 + k0 + ((lane >> 4) << 3)) * 2;
            ldsm4(Ph, sb + AT_PH * 2 + aoff);
            ldsm4(Pl, sb + AT_PL * 2 + aoff);
            const int krow = k0 + (lane & 15);
            const int soff = ((lane >> 4) << 3);
#pragma unroll
            for (int j = 0; j < 4; j++) {
                uint32_t Vh[4], Vl[4];
                const uint32_t boff = (krow * 136 + nb + j * 16 + soff) * 2;
                ldsm4t(Vh, sb + AT_QH * 2 + boff);
                ldsm4t(Vl, sb + AT_QL * 2 + boff);
#pragma unroll
                for (int h = 0; h < 2; h++) {
                    mma16816(acc[j * 2 + h], Ph, &Vh[h * 2]);
                    mma16816(acc[j * 2 + h], Ph, &Vl[h * 2]);
                    mma16816(acc[j * 2 + h], Pl, &Vh[h * 2]);
                }
            }
        }
        // epilogue: out[b][c][s*128 + t]
        const int g = lane >> 2, t = lane & 3;
        const long obase = (long)b * 64 * HW + (long)s * SDIM;
#pragma unroll
        for (int n = 0; n < 8; n++) {
            int col = nb + n * 8 + 2 * t;
            int r0 = mw * 16 + g, r1 = r0 + 8;
            *(float2*)&outp[obase + (long)r0 * HW + col] = make_float2(acc[n][0], acc[n][1]);
            *(float2*)&outp[obase + (long)r1 * HW + col] = make_float2(acc[n][2], acc[n][3]);
        }
    }
}

// ================= combine + bf16 split (fused) =================
__global__ __launch_bounds__(256) void combine_split(const float* __restrict__ outV,
                                                     const float* __restrict__ outT,
                                                     const float* __restrict__ gamma,
                                                     __nv_bfloat16* __restrict__ Sh,
                                                     __nv_bfloat16* __restrict__ Sl)
{
    __shared__ float tile[32][33];
    const long base = (long)blockIdx.z * HW;
    const int bx = blockIdx.x * 32;
    const int by = blockIdx.y * 32;
    const int tx = threadIdx.x;
    const int ty = threadIdx.y;
    const float g = *gamma;

#pragma unroll
    for (int i = 0; i < 32; i += 8)
        tile[ty + i][tx] = outT[base + (long)(by + ty + i) * SDIM + bx + tx];
    __syncthreads();
#pragma unroll
    for (int i = 0; i < 32; i += 8) {
        long idx = base + (long)(bx + ty + i) * SDIM + by + tx;
        float v = g * (outV[idx] + tile[tx][ty + i]);
        __nv_bfloat16 h = __float2bfloat16_rn(v);
        Sh[idx] = h;
        Sl[idx] = __float2bfloat16_rn(v - __bfloat162float(h));
    }
}

// ================= launch =================
extern "C" void kernel_launch(void* const* d_in, const int* in_sizes, int n_in,
                              void* d_out, int out_size)
{
    const float* x      = (const float*)d_in[0];
    const float* qkv_w  = (const float*)d_in[1];
    const float* qkv_b  = (const float*)d_in[2];
    const float* out_w  = (const float*)d_in[3];
    const float* out_b  = (const float*)d_in[4];
    const float* gamma  = (const float*)d_in[5];
    float* out = (float*)d_out;
    (void)in_sizes; (void)n_in; (void)out_size;

    float *qkvp, *qkvTp, *outTp, *outVp;
    __nv_bfloat16 *wqh, *wql, *woh, *wol, *shp, *slp;
    cudaGetSymbolAddress((void**)&qkvp,  g_qkv);
    cudaGetSymbolAddress((void**)&qkvTp, g_qkvT);
    cudaGetSymbolAddress((void**)&outTp, g_outT);
    cudaGetSymbolAddress((void**)&outVp, g_outV);
    cudaGetSymbolAddress((void**)&wqh, g_wq_hi);
    cudaGetSymbolAddress((void**)&wql, g_wq_lo);
    cudaGetSymbolAddress((void**)&woh, g_wo_hi);
    cudaGetSymbolAddress((void**)&wol, g_wo_lo);
    cudaGetSymbolAddress((void**)&shp, g_sh);
    cudaGetSymbolAddress((void**)&slp, g_sl);

    cudaFuncSetAttribute(attn_hmma, cudaFuncAttributeMaxDynamicSharedMemorySize, AT_SMEM);
    cudaFuncSetAttribute(gemm1_hmma, cudaFuncAttributeMaxDynamicSharedMemorySize, G1_SMEM);
    cudaFuncSetAttribute(gemm2_hmma, cudaFuncAttributeMaxDynamicSharedMemorySize, G2_SMEM);

    split_mat<<<(192 * 512 + 255) / 256, 256>>>(qkv_w, wqh, wql, 192 * 512);
    split_mat<<<(512 * 64 + 255) / 256, 256>>>(out_w, woh, wol, 512 * 64);
    gemm1_hmma<<<dim3(128, 8), 256, G1_SMEM>>>(wqh, wql, x, qkv_b, qkvp);
    transpose_hw<<<dim3(4, 4, 8 * 192), dim3(32, 8)>>>(qkvp, qkvTp);
    attn_hmma<<<dim3(128, 8), 256, AT_SMEM>>>(qkvTp, outTp);
    attn_hmma<<<dim3(128, 8), 256, AT_SMEM>>>(qkvp, outVp);
    combine_split<<<dim3(4, 4, 8 * 64), dim3(32, 8)>>>(outVp, outTp, gamma, shp, slp);
    gemm2_hmma<<<dim3(128, 4, 8), 256, G2_SMEM>>>(woh, wol, shp, slp, out_b, x, out);
}

// round 5
// speedup vs baseline: 2.6485x; 1.0054x over previous
#include <cuda_runtime.h>
#include <cuda_bf16.h>
#include <math.h>
#include <stdint.h>

#define HW 16384   // 128*128
#define SDIM 128

// ================= scratch =================
__device__ float g_qkv [8L * 192 * HW];   // [b][192][s]
__device__ float g_qkvT[8L * 192 * HW];   // [b][192][w][h]
__device__ float g_outT[8L * 64 * HW];    // horizontal branch, [b][c][w][h]
__device__ float g_outV[8L * 64 * HW];    // vertical branch,   [b][c][h][w]
__device__ __nv_bfloat16 g_sh[8L * 64 * HW];  // gamma*(h+v) bf16 hi, [b][c][s]
__device__ __nv_bfloat16 g_sl[8L * 64 * HW];  // bf16 lo
__device__ __nv_bfloat16 g_wq_hi[192 * 512], g_wq_lo[192 * 512];
__device__ __nv_bfloat16 g_wo_hi[512 * 64],  g_wo_lo[512 * 64];

// ================= mma helpers =================
__device__ __forceinline__ uint32_t smem_u32(const void* p) {
    uint32_t a;
    asm("{ .reg .u64 t; cvta.to.shared.u64 t, %1; cvt.u32.u64 %0, t; }" : "=r"(a) : "l"(p));
    return a;
}
__device__ __forceinline__ void ldsm4(uint32_t r[4], uint32_t a) {
    asm volatile("ldmatrix.sync.aligned.m8n8.x4.shared.b16 {%0,%1,%2,%3}, [%4];"
        : "=r"(r[0]), "=r"(r[1]), "=r"(r[2]), "=r"(r[3]) : "r"(a));
}
__device__ __forceinline__ void ldsm4t(uint32_t r[4], uint32_t a) {
    asm volatile("ldmatrix.sync.aligned.m8n8.x4.trans.shared.b16 {%0,%1,%2,%3}, [%4];"
        : "=r"(r[0]), "=r"(r[1]), "=r"(r[2]), "=r"(r[3]) : "r"(a));
}
// B-operand fragments for row.col mma from ROW-MAJOR [n][k] storage.
__device__ __forceinline__ void ldsm4_bnk(uint32_t r[4], uint32_t base_bytes, int pitch_bytes) {
    int lane = threadIdx.x & 31;
    int rr = lane & 7, grp = lane >> 3;
    int n = rr + ((grp & 2) ? 8 : 0);
    int k = (grp & 1) ? 8 : 0;
    ldsm4(r, base_bytes + n * pitch_bytes + k * 2);
}
__device__ __forceinline__ void mma16816(float c[4], const uint32_t a[4], const uint32_t b[2]) {
    asm volatile("mma.sync.aligned.m16n8k16.row.col.f32.bf16.bf16.f32 "
        "{%0,%1,%2,%3}, {%4,%5,%6,%7}, {%8,%9}, {%0,%1,%2,%3};"
        : "+f"(c[0]), "+f"(c[1]), "+f"(c[2]), "+f"(c[3])
        : "r"(a[0]), "r"(a[1]), "r"(a[2]), "r"(a[3]), "r"(b[0]), "r"(b[1]));
}
__device__ __forceinline__ void cp16(uint32_t d, const void* s) {
    asm volatile("cp.async.ca.shared.global [%0], [%1], 16;" :: "r"(d), "l"(s));
}
#define CP_COMMIT() asm volatile("cp.async.commit_group;" ::: "memory")
#define CP_WAIT0()  asm volatile("cp.async.wait_group 0;" ::: "memory")

__device__ __forceinline__ uint32_t pk(__nv_bfloat16 a, __nv_bfloat16 b) {
    __nv_bfloat162 t; t.x = a; t.y = b;
    return *reinterpret_cast<uint32_t*>(&t);
}
__device__ __forceinline__ void split4(float4 v, uint2& hi, uint2& lo) {
    __nv_bfloat16 h0 = __float2bfloat16_rn(v.x), h1 = __float2bfloat16_rn(v.y);
    __nv_bfloat16 h2 = __float2bfloat16_rn(v.z), h3 = __float2bfloat16_rn(v.w);
    __nv_bfloat16 l0 = __float2bfloat16_rn(v.x - __bfloat162float(h0));
    __nv_bfloat16 l1 = __float2bfloat16_rn(v.y - __bfloat162float(h1));
    __nv_bfloat16 l2 = __float2bfloat16_rn(v.z - __bfloat162float(h2));
    __nv_bfloat16 l3 = __float2bfloat16_rn(v.w - __bfloat162float(h3));
    hi = make_uint2(pk(h0, h1), pk(h2, h3));
    lo = make_uint2(pk(l0, l1), pk(l2, l3));
}

// ================= weight split =================
__global__ __launch_bounds__(256) void split_mat(const float* __restrict__ src,
                                                 __nv_bfloat16* __restrict__ hi,
                                                 __nv_bfloat16* __restrict__ lo, int n)
{
    int i = blockIdx.x * 256 + threadIdx.x;
    if (i < n) {
        float v = src[i];
        __nv_bfloat16 h = __float2bfloat16_rn(v);
        hi[i] = h;
        lo[i] = __float2bfloat16_rn(v - __bfloat162float(h));
    }
}

// ================= GEMM1: n=64 tile, 2 blocks/SM =================
// A = Wq hi/lo (192 x 512, K-major). B = x chunk converted in-kernel to bf16 [c][s].
// block: 192 o x 64 s; K in 16 chunks of 32; double-buffered smem.
#define G1_WH 0
#define G1_WL 7680
#define G1_XH 15360
#define G1_XL 17664
#define G1_BUF 19968
#define G1_SMEM (2 * G1_BUF * 2)   // 79872 bytes

__global__ __launch_bounds__(256, 2) void gemm1_hmma(
    const __nv_bfloat16* __restrict__ Wh, const __nv_bfloat16* __restrict__ Wl,
    const float* __restrict__ x, const float* __restrict__ bias,
    float* __restrict__ outp)
{
    extern __shared__ __nv_bfloat16 sm[];
    const uint32_t sb = smem_u32(sm);
    const int tid = threadIdx.x;
    const int b = blockIdx.y;
    const int s0 = blockIdx.x * 64;
    const float* xb = x + (long)b * 512 * HW;

    const int warp = tid >> 5, lane = tid & 31;
    const int obase = (warp >> 1) * 48;   // 3 m16 tiles per warp
    const int nbase = (warp & 1) * 32;    // 4 n8 tiles per warp

    float acc[3][4][4];
#pragma unroll
    for (int m = 0; m < 3; m++)
#pragma unroll
        for (int n = 0; n < 4; n++)
#pragma unroll
            for (int q = 0; q < 4; q++) acc[m][n][q] = 0.f;

    float4 xr[2];

    // ---- prologue: chunk 0 into buf 0 ----
#pragma unroll
    for (int i = 0; i < 3; i++) {
        int fi = tid + i * 256;
        int row = fi >> 2, g = fi & 3;
        cp16(sb + (G1_WH + row * 40 + g * 8) * 2, Wh + row * 512 + g * 8);
        cp16(sb + (G1_WL + row * 40 + g * 8) * 2, Wl + row * 512 + g * 8);
    }
    CP_COMMIT();
#pragma unroll
    for (int i = 0; i < 2; i++) {
        int fi = tid + i * 256;
        int row = fi >> 4, c4 = (fi & 15) * 4;
        xr[i] = *(const float4*)&xb[(long)row * HW + s0 + c4];
    }
#pragma unroll
    for (int i = 0; i < 2; i++) {
        int fi = tid + i * 256;
        int row = fi >> 4, c4 = (fi & 15) * 4;
        uint2 hi, lo; split4(xr[i], hi, lo);
        *(uint2*)&sm[G1_XH + row * 72 + c4] = hi;
        *(uint2*)&sm[G1_XL + row * 72 + c4] = lo;
    }
    CP_WAIT0();
    __syncthreads();

    for (int ch = 0; ch < 16; ch++) {
        const int cur = ch & 1, nxt = cur ^ 1;
        if (ch < 15) {
            const int c0n = (ch + 1) * 32;
#pragma unroll
            for (int i = 0; i < 3; i++) {
                int fi = tid + i * 256;
                int row = fi >> 2, g = fi & 3;
                cp16(sb + (nxt * G1_BUF + G1_WH + row * 40 + g * 8) * 2, Wh + row * 512 + c0n + g * 8);
                cp16(sb + (nxt * G1_BUF + G1_WL + row * 40 + g * 8) * 2, Wl + row * 512 + c0n + g * 8);
            }
            CP_COMMIT();
#pragma unroll
            for (int i = 0; i < 2; i++) {
                int fi = tid + i * 256;
                int row = fi >> 4, c4 = (fi & 15) * 4;
                xr[i] = *(const float4*)&xb[(long)(c0n + row) * HW + s0 + c4];
            }
        }
        // ---- compute chunk ch (2 k16 steps) ----
        const uint32_t wb = sb + (cur * G1_BUF) * 2;
#pragma unroll
        for (int k0 = 0; k0 < 32; k0 += 16) {
            uint32_t Ah[3][4], Al[3][4], B[2][4];
            const int arow = (lane & 15);
            const int acol = k0 + ((lane >> 4) << 3);
#pragma unroll
            for (int m = 0; m < 3; m++) {
                ldsm4(Ah[m], wb + (G1_WH + (obase + m * 16 + arow) * 40 + acol) * 2);
                ldsm4(Al[m], wb + (G1_WL + (obase + m * 16 + arow) * 40 + acol) * 2);
            }
            const int krow = k0 + (lane & 15);
            const int soff = ((lane >> 4) << 3);
#pragma unroll
            for (int j = 0; j < 2; j++)
                ldsm4t(B[j], wb + (G1_XH + krow * 72 + nbase + j * 16 + soff) * 2);
#pragma unroll
            for (int m = 0; m < 3; m++)
#pragma unroll
                for (int j = 0; j < 2; j++) {
                    mma16816(acc[m][2 * j],     Ah[m], &B[j][0]);
                    mma16816(acc[m][2 * j + 1], Ah[m], &B[j][2]);
                }
#pragma unroll
            for (int m = 0; m < 3; m++)
#pragma unroll
                for (int j = 0; j < 2; j++) {
                    mma16816(acc[m][2 * j],     Al[m], &B[j][0]);
                    mma16816(acc[m][2 * j + 1], Al[m], &B[j][2]);
                }
#pragma unroll
            for (int j = 0; j < 2; j++)
                ldsm4t(B[j], wb + (G1_XL + krow * 72 + nbase + j * 16 + soff) * 2);
#pragma unroll
            for (int m = 0; m < 3; m++)
#pragma unroll
                for (int j = 0; j < 2; j++) {
                    mma16816(acc[m][2 * j],     Ah[m], &B[j][0]);
                    mma16816(acc[m][2 * j + 1], Ah[m], &B[j][2]);
                }
        }
        if (ch < 15) {
#pragma unroll
            for (int i = 0; i < 2; i++) {
                int fi = tid + i * 256;
                int row = fi >> 4, c4 = (fi & 15) * 4;
                uint2 hi, lo; split4(xr[i], hi, lo);
                *(uint2*)&sm[nxt * G1_BUF + G1_XH + row * 72 + c4] = hi;
                *(uint2*)&sm[nxt * G1_BUF + G1_XL + row * 72 + c4] = lo;
            }
        }
        CP_WAIT0();
        __syncthreads();
    }

    // ---- epilogue: C[o][s] + bias ----
    const int g = lane >> 2, t = lane & 3;
    const long ob = (long)b * 192 * HW;
#pragma unroll
    for (int m = 0; m < 3; m++) {
        int o = obase + m * 16 + g;
        float b0 = bias[o], b1 = bias[o + 8];
#pragma unroll
        for (int n = 0; n < 4; n++) {
            int s = s0 + nbase + n * 8 + 2 * t;
            float2 v0 = make_float2(acc[m][n][0] + b0, acc[m][n][1] + b0);
            float2 v1 = make_float2(acc[m][n][2] + b1, acc[m][n][3] + b1);
            *(float2*)&outp[ob + (long)o * HW + s] = v0;
            *(float2*)&outp[ob + (long)(o + 8) * HW + s] = v1;
        }
    }
}

// ================= GEMM2 (unchanged) =================
#define G2_AH 0
#define G2_AL 9216
#define G2_SH 18432
#define G2_SL 27136
#define G2_SMEM (35840 * 2)

__global__ __launch_bounds__(256) void gemm2_hmma(
    const __nv_bfloat16* __restrict__ Wh, const __nv_bfloat16* __restrict__ Wl,
    const __nv_bfloat16* __restrict__ Sh, const __nv_bfloat16* __restrict__ Sl,
    const float* __restrict__ bias, const float* __restrict__ resid,
    float* __restrict__ outp)
{
    extern __shared__ __nv_bfloat16 sm[];
    const uint32_t sb = smem_u32(sm);
    const int tid = threadIdx.x;
    const int b = blockIdx.z;
    const int o0 = blockIdx.y * 128;
    const int s0 = blockIdx.x * 128;

#pragma unroll
    for (int i = 0; i < 4; i++) {
        int fi = tid + i * 256;
        int row = fi >> 3, gq = fi & 7;
        *(uint4*)&sm[G2_AH + row * 72 + gq * 8] = *(const uint4*)&Wh[(o0 + row) * 64 + gq * 8];
        *(uint4*)&sm[G2_AL + row * 72 + gq * 8] = *(const uint4*)&Wl[(o0 + row) * 64 + gq * 8];
    }
#pragma unroll
    for (int i = 0; i < 4; i++) {
        int fi = tid + i * 256;
        int row = fi >> 4, gq = fi & 15;
        *(uint4*)&sm[G2_SH + row * 136 + gq * 8] = *(const uint4*)&Sh[((long)b * 64 + row) * HW + s0 + gq * 8];
        *(uint4*)&sm[G2_SL + row * 136 + gq * 8] = *(const uint4*)&Sl[((long)b * 64 + row) * HW + s0 + gq * 8];
    }
    __syncthreads();

    const int warp = tid >> 5, lane = tid & 31;
    const int obase = (warp >> 1) * 32;
    const int sbase = (warp & 1) * 64;

    float acc[2][8][4];
#pragma unroll
    for (int m = 0; m < 2; m++)
#pragma unroll
        for (int n = 0; n < 8; n++)
#pragma unroll
            for (int q = 0; q < 4; q++) acc[m][n][q] = 0.f;

#pragma unroll
    for (int k0 = 0; k0 < 64; k0 += 16) {
        uint32_t Ah[2][4], Al[2][4], B[4][4];
        const int arow = (lane & 15);
        const int acol = k0 + ((lane >> 4) << 3);
#pragma unroll
        for (int m = 0; m < 2; m++) {
            ldsm4(Ah[m], sb + (G2_AH + (obase + m * 16 + arow) * 72 + acol) * 2);
            ldsm4(Al[m], sb + (G2_AL + (obase + m * 16 + arow) * 72 + acol) * 2);
        }
        const int krow = k0 + (lane & 15);
        const int soff = ((lane >> 4) << 3);
#pragma unroll
        for (int j = 0; j < 4; j++)
            ldsm4t(B[j], sb + (G2_SH + krow * 136 + sbase + j * 16 + soff) * 2);
#pragma unroll
        for (int m = 0; m < 2; m++)
#pragma unroll
            for (int j = 0; j < 4; j++) {
                mma16816(acc[m][2 * j],     Ah[m], &B[j][0]);
                mma16816(acc[m][2 * j + 1], Ah[m], &B[j][2]);
            }
#pragma unroll
        for (int m = 0; m < 2; m++)
#pragma unroll
            for (int j = 0; j < 4; j++) {
                mma16816(acc[m][2 * j],     Al[m], &B[j][0]);
                mma16816(acc[m][2 * j + 1], Al[m], &B[j][2]);
            }
#pragma unroll
        for (int j = 0; j < 4; j++)
            ldsm4t(B[j], sb + (G2_SL + krow * 136 + sbase + j * 16 + soff) * 2);
#pragma unroll
        for (int m = 0; m < 2; m++)
#pragma unroll
            for (int j = 0; j < 4; j++) {
                mma16816(acc[m][2 * j],     Ah[m], &B[j][0]);
                mma16816(acc[m][2 * j + 1], Ah[m], &B[j][2]);
            }
    }

    const int g = lane >> 2, t = lane & 3;
#pragma unroll
    for (int m = 0; m < 2; m++) {
        int o = o0 + obase + m * 16 + g;
        float b0 = bias[o], b1 = bias[o + 8];
#pragma unroll
        for (int n = 0; n < 8; n++) {
            int s = s0 + sbase + n * 8 + 2 * t;
            long i0 = ((long)b * 512 + o) * HW + s;
            long i1 = ((long)b * 512 + o + 8) * HW + s;
            float2 r0 = *(const float2*)&resid[i0];
            float2 r1 = *(const float2*)&resid[i1];
            float2 v0 = make_float2(acc[m][n][0] + b0 + r0.x, acc[m][n][1] + b0 + r0.y);
            float2 v1 = make_float2(acc[m][n][2] + b1 + r1.x, acc[m][n][3] + b1 + r1.y);
            *(float2*)&outp[i0] = v0;
            *(float2*)&outp[i1] = v1;
        }
    }
}

// ================= 128x128 HW-transpose per slice =================
__global__ __launch_bounds__(256) void transpose_hw(const float* __restrict__ in,
                                                    float* __restrict__ out)
{
    __shared__ float tile[32][33];
    const long base = (long)blockIdx.z * HW;
    const int bx = blockIdx.x * 32;
    const int by = blockIdx.y * 32;
    const int tx = threadIdx.x;
    const int ty = threadIdx.y;
#pragma unroll
    for (int i = 0; i < 32; i += 8)
        tile[ty + i][tx] = in[base + (long)(by + ty + i) * SDIM + bx + tx];
    __syncthreads();
#pragma unroll
    for (int i = 0; i < 32; i += 8)
        out[base + (long)(bx + ty + i) * SDIM + by + tx] = tile[tx][ty + i];
}

// ================= HMMA attention branch =================
#define AT_QH 0
#define AT_QL 8704
#define AT_KH 17408
#define AT_KL 26112
#define AT_ES 34816
#define AT_PH 43136
#define AT_PL 47744
#define AT_SMEM (52352 * 2)   // 104704 bytes

__global__ __launch_bounds__(256, 2) void attn_hmma(const float* __restrict__ qkv,
                                                    float* __restrict__ outp)
{
    extern __shared__ __nv_bfloat16 sm[];
    const uint32_t sb = smem_u32(sm);
    float* Ef = (float*)(sm + AT_ES);

    const int b = blockIdx.y;
    const int s = blockIdx.x;
    const int tid = threadIdx.x;
    const int warp = tid >> 5, lane = tid & 31;
    const long base = (long)b * 192 * HW + (long)s * SDIM;

    // --- stage Q, K as bf16 hi/lo ---
#pragma unroll
    for (int t = 0; t < 8; t++) {
        int fi = tid + t * 256;
        int row = fi >> 5, c4 = (fi & 31) * 4;
        float4 qv = *(const float4*)&qkv[base + (long)row * HW + c4];
        float4 kv = *(const float4*)&qkv[base + (long)(row + 64) * HW + c4];
        uint2 hi, lo;
        split4(qv, hi, lo);
        *(uint2*)&sm[AT_QH + row * 136 + c4] = hi;
        *(uint2*)&sm[AT_QL + row * 136 + c4] = lo;
        split4(kv, hi, lo);
        *(uint2*)&sm[AT_KH + row * 136 + c4] = hi;
        *(uint2*)&sm[AT_KL + row * 136 + c4] = lo;
    }
    __syncthreads();

    // --- E = Q.K^T (bf16x3) ---
    {
        const int mw = warp >> 1;
        const int nb = (warp & 1) * 32;
        float eacc[4][4];
#pragma unroll
        for (int i = 0; i < 4; i++)
#pragma unroll
            for (int q = 0; q < 4; q++) eacc[i][q] = 0.f;

#pragma unroll
        for (int k0 = 0; k0 < 128; k0 += 16) {
            uint32_t Ah[4], Al[4];
            const uint32_t aoff = ((mw * 16 + (lane & 15)) * 136 + k0 + ((lane >> 4) << 3)) * 2;
            ldsm4(Ah, sb + AT_QH * 2 + aoff);
            ldsm4(Al, sb + AT_QL * 2 + aoff);
#pragma unroll
            for (int j = 0; j < 2; j++) {
                uint32_t Bh[4], Bl[4];
                const uint32_t bbase = ((nb + j * 16) * 136 + k0) * 2;
                ldsm4_bnk(Bh, sb + AT_KH * 2 + bbase, 272);
                ldsm4_bnk(Bl, sb + AT_KL * 2 + bbase, 272);
#pragma unroll
                for (int h = 0; h < 2; h++) {
                    mma16816(eacc[j * 2 + h], Ah, &Bh[h * 2]);
                    mma16816(eacc[j * 2 + h], Ah, &Bl[h * 2]);
                    mma16816(eacc[j * 2 + h], Al, &Bh[h * 2]);
                }
            }
        }
        const int g = lane >> 2, t = lane & 3;
#pragma unroll
        for (int j = 0; j < 2; j++)
#pragma unroll
            for (int h = 0; h < 2; h++) {
                int n = nb + j * 16 + h * 8 + 2 * t;
                int tt = j * 2 + h;
                Ef[(mw * 16 + g) * 65 + n]     = eacc[tt][0];
                Ef[(mw * 16 + g) * 65 + n + 1] = eacc[tt][1];
                Ef[(mw * 16 + g + 8) * 65 + n]     = eacc[tt][2];
                Ef[(mw * 16 + g + 8) * 65 + n + 1] = eacc[tt][3];
            }
    }
    __syncthreads();

    // --- stage V; softmax (4 threads/row, fused P bf16 split) ---
#pragma unroll
    for (int t = 0; t < 8; t++) {
        int fi = tid + t * 256;
        int row = fi >> 5, c4 = (fi & 31) * 4;
        float4 vv = *(const float4*)&qkv[base + (long)(row + 128) * HW + c4];
        uint2 hi, lo; split4(vv, hi, lo);
        *(uint2*)&sm[AT_QH + row * 136 + c4] = hi;
        *(uint2*)&sm[AT_QL + row * 136 + c4] = lo;
    }
    {
        const int row = tid >> 2, t4 = tid & 3;
        float* er = &Ef[row * 65 + t4 * 16];
        float e[16];
        float m = -INFINITY;
#pragma unroll
        for (int j = 0; j < 16; j++) { e[j] = er[j]; m = fmaxf(m, e[j]); }
        m = fmaxf(m, __shfl_xor_sync(0xFFFFFFFFu, m, 1));
        m = fmaxf(m, __shfl_xor_sync(0xFFFFFFFFu, m, 2));
        float ssum = 0.f;
#pragma unroll
        for (int j = 0; j < 16; j++) { e[j] = __expf(e[j] - m); ssum += e[j]; }
        ssum += __shfl_xor_sync(0xFFFFFFFFu, ssum, 1);
        ssum += __shfl_xor_sync(0xFFFFFFFFu, ssum, 2);
        float inv = 1.f / ssum;
#pragma unroll
        for (int c = 0; c < 16; c += 4) {
            float4 v = make_float4(e[c] * inv, e[c + 1] * inv, e[c + 2] * inv, e[c + 3] * inv);
            uint2 hi, lo; split4(v, hi, lo);
            *(uint2*)&sm[AT_PH + row * 72 + t4 * 16 + c] = hi;
            *(uint2*)&sm[AT_PL + row * 72 + t4 * 16 + c] = lo;
        }
    }
    __syncthreads();

    // --- out = P.V (bf16x3) ---
    {
        const int mw = warp >> 1;
        const int nb = (warp & 1) * 64;
        float acc[8][4];
#pragma unroll
        for (int n = 0; n < 8; n++)
#pragma unroll
            for (int q = 0; q < 4; q++) acc[n][q] = 0.f;

#pragma unroll
        for (int k0 = 0; k0 < 64; k0 += 16) {
            uint32_t Ph[4], Pl[4];
            const uint32_t aoff = ((mw * 16 + (lane & 15)) * 72 + k0 + ((lane >> 4) << 3)) * 2;
            ldsm4(Ph, sb + AT_PH * 2 + aoff);
            ldsm4(Pl, sb + AT_PL * 2 + aoff);
            const int krow = k0 + (lane & 15);
            const int soff = ((lane >> 4) << 3);
#pragma unroll
            for (int j = 0; j < 4; j++) {
                uint32_t Vh[4], Vl[4];
                const uint32_t boff = (krow * 136 + nb + j * 16 + soff) * 2;
                ldsm4t(Vh, sb + AT_QH * 2 + boff);
                ldsm4t(Vl, sb + AT_QL * 2 + boff);
#pragma unroll
                for (int h = 0; h < 2; h++) {
                    mma16816(acc[j * 2 + h], Ph, &Vh[h * 2]);
                    mma16816(acc[j * 2 + h], Ph, &Vl[h * 2]);
                    mma16816(acc[j * 2 + h], Pl, &Vh[h * 2]);
                }
            }
        }
        const int g = lane >> 2, t = lane & 3;
        const long obase = (long)b * 64 * HW + (long)s * SDIM;
#pragma unroll
        for (int n = 0; n < 8; n++) {
            int col = nb + n * 8 + 2 * t;
            int r0 = mw * 16 + g, r1 = r0 + 8;
            *(float2*)&outp[obase + (long)r0 * HW + col] = make_float2(acc[n][0], acc[n][1]);
            *(float2*)&outp[obase + (long)r1 * HW + col] = make_float2(acc[n][2], acc[n][3]);
        }
    }
}

// ================= combine + bf16 split (fused) =================
__global__ __launch_bounds__(256) void combine_split(const float* __restrict__ outV,
                                                     const float* __restrict__ outT,
                                                     const float* __restrict__ gamma,
                                                     __nv_bfloat16* __restrict__ Sh,
                                                     __nv_bfloat16* __restrict__ Sl)
{
    __shared__ float tile[32][33];
    const long base = (long)blockIdx.z * HW;
    const int bx = blockIdx.x * 32;
    const int by = blockIdx.y * 32;
    const int tx = threadIdx.x;
    const int ty = threadIdx.y;
    const float g = *gamma;

#pragma unroll
    for (int i = 0; i < 32; i += 8)
        tile[ty + i][tx] = outT[base + (long)(by + ty + i) * SDIM + bx + tx];
    __syncthreads();
#pragma unroll
    for (int i = 0; i < 32; i += 8) {
        long idx = base + (long)(bx + ty + i) * SDIM + by + tx;
        float v = g * (outV[idx] + tile[tx][ty + i]);
        __nv_bfloat16 h = __float2bfloat16_rn(v);
        Sh[idx] = h;
        Sl[idx] = __float2bfloat16_rn(v - __bfloat162float(h));
    }
}

// ================= launch =================
extern "C" void kernel_launch(void* const* d_in, const int* in_sizes, int n_in,
                              void* d_out, int out_size)
{
    const float* x      = (const float*)d_in[0];
    const float* qkv_w  = (const float*)d_in[1];
    const float* qkv_b  = (const float*)d_in[2];
    const float* out_w  = (const float*)d_in[3];
    const float* out_b  = (const float*)d_in[4];
    const float* gamma  = (const float*)d_in[5];
    float* out = (float*)d_out;
    (void)in_sizes; (void)n_in; (void)out_size;

    float *qkvp, *qkvTp, *outTp, *outVp;
    __nv_bfloat16 *wqh, *wql, *woh, *wol, *shp, *slp;
    cudaGetSymbolAddress((void**)&qkvp,  g_qkv);
    cudaGetSymbolAddress((void**)&qkvTp, g_qkvT);
    cudaGetSymbolAddress((void**)&outTp, g_outT);
    cudaGetSymbolAddress((void**)&outVp, g_outV);
    cudaGetSymbolAddress((void**)&wqh, g_wq_hi);
    cudaGetSymbolAddress((void**)&wql, g_wq_lo);
    cudaGetSymbolAddress((void**)&woh, g_wo_hi);
    cudaGetSymbolAddress((void**)&wol, g_wo_lo);
    cudaGetSymbolAddress((void**)&shp, g_sh);
    cudaGetSymbolAddress((void**)&slp, g_sl);

    cudaFuncSetAttribute(attn_hmma, cudaFuncAttributeMaxDynamicSharedMemorySize, AT_SMEM);
    cudaFuncSetAttribute(gemm1_hmma, cudaFuncAttributeMaxDynamicSharedMemorySize, G1_SMEM);
    cudaFuncSetAttribute(gemm2_hmma, cudaFuncAttributeMaxDynamicSharedMemorySize, G2_SMEM);

    split_mat<<<(192 * 512 + 255) / 256, 256>>>(qkv_w, wqh, wql, 192 * 512);
    split_mat<<<(512 * 64 + 255) / 256, 256>>>(out_w, woh, wol, 512 * 64);
    gemm1_hmma<<<dim3(256, 8), 256, G1_SMEM>>>(wqh, wql, x, qkv_b, qkvp);
    transpose_hw<<<dim3(4, 4, 8 * 192), dim3(32, 8)>>>(qkvp, qkvTp);
    attn_hmma<<<dim3(128, 8), 256, AT_SMEM>>>(qkvTp, outTp);
    attn_hmma<<<dim3(128, 8), 256, AT_SMEM>>>(qkvp, outVp);
    combine_split<<<dim3(4, 4, 8 * 64), dim3(32, 8)>>>(outVp, outTp, gamma, shp, slp);
    gemm2_hmma<<<dim3(128, 4, 8), 256, G2_SMEM>>>(woh, wol, shp, slp, out_b, x, out);
}